// round 8
// baseline (speedup 1.0000x reference)
#include <cuda_runtime.h>
#include <math.h>

#define BB 2
#define SS 1024
#define DD 1024
#define HH 16
#define HD 64
#define LL 4
#define FFD 2816
#define VV 32000
#define MROWS (BB*SS)   // 2048
#define EPSV 1e-6f

// ---------------- scratch (device globals; no allocations) ----------------
__device__ float g_h  [MROWS*DD];
__device__ float g_hn [MROWS*DD];
__device__ float g_q  [MROWS*DD];
__device__ float g_k  [MROWS*DD];
__device__ float g_v  [MROWS*DD];
__device__ float g_ao [MROWS*DD];
__device__ float g_f1 [MROWS*FFD];
__device__ float g_f3 [MROWS*FFD];
__device__ float g_cos[SS*(HD/2)];
__device__ float g_sin[SS*(HD/2)];

// ---------------- small elementwise kernels ----------------
__global__ void rope_tables_kernel() {
    int idx = blockIdx.x*blockDim.x + threadIdx.x;
    if (idx >= SS*(HD/2)) return;
    int s = idx / (HD/2);
    int j = idx % (HD/2);
    float inv = powf(10000.0f, -2.0f*(float)j/(float)HD);
    float ang = (float)s * inv;
    g_cos[idx] = cosf(ang);
    g_sin[idx] = sinf(ang);
}

__global__ void embed_kernel(const int* __restrict__ tokens, const float* __restrict__ emb) {
    int idx = blockIdx.x*blockDim.x + threadIdx.x;
    if (idx >= MROWS*DD) return;
    int row = idx / DD;
    int d   = idx % DD;
    g_h[idx] = emb[(size_t)tokens[row]*DD + d];
}

__global__ void rope_kernel(float* __restrict__ x) {
    int idx = blockIdx.x*blockDim.x + threadIdx.x;
    const int total = BB*SS*HH*(HD/2);
    if (idx >= total) return;
    int j = idx % (HD/2);
    int h = (idx/(HD/2)) % HH;
    int s = (idx/(HD/2)/HH) % SS;
    int b =  idx/(HD/2)/HH/SS;
    float c  = g_cos[s*(HD/2)+j];
    float sn = g_sin[s*(HD/2)+j];
    size_t base = (size_t)(b*SS+s)*DD + h*HD + 2*j;
    float x0 = x[base], x1 = x[base+1];
    x[base]   = x0*c - x1*sn;
    x[base+1] = x0*sn + x1*c;
}

__global__ void rmsnorm_kernel(const float* __restrict__ x, const float* __restrict__ w,
                               float* __restrict__ out) {
    int row = blockIdx.x;
    int t   = threadIdx.x;
    const float* xr = x + (size_t)row*DD;
    float v[4];
    float ss = 0.f;
    #pragma unroll
    for (int e = 0; e < 4; e++) { v[e] = xr[t + e*256]; ss += v[e]*v[e]; }
    __shared__ float red[256];
    red[t] = ss; __syncthreads();
    for (int off = 128; off > 0; off >>= 1) {
        if (t < off) red[t] += red[t+off];
        __syncthreads();
    }
    float scale = rsqrtf(red[0]/(float)DD + EPSV);
    #pragma unroll
    for (int e = 0; e < 4; e++) {
        int d = t + e*256;
        out[(size_t)row*DD + d] = v[e]*scale*w[d];
    }
}

__global__ void silu_mul_kernel() {
    int idx = blockIdx.x*blockDim.x + threadIdx.x;
    if (idx >= MROWS*FFD) return;
    float a = g_f1[idx];
    float sig = 1.0f / (1.0f + __expf(-a));
    g_f1[idx] = a*sig*g_f3[idx];
}

// ---------------- 3xTF32 tensor-core GEMM, smem-resident hi/lo split ----------------
// C[M,N] = A[M,K] @ op(B);  TRANSB=0: B[K,N];  TRANSB=1: B[N,K] (C = A @ B^T)
// Block tile 128x128, K-chunk 16, 8 warps 4(m)x2(n), warp tile 32x64, m16n8k8 tf32.
// smem holds interleaved (hi, lo) TF32 pairs: [k][2*idx+{0,1}], width 264 floats.

__device__ __forceinline__ unsigned f2tf(float f) {
    unsigned u;
    asm("cvt.rna.tf32.f32 %0, %1;" : "=r"(u) : "f"(f));
    return u;
}

__device__ __forceinline__ float2 split_tf2(float f) {
    unsigned hi = f2tf(f);
    unsigned lo = f2tf(f - __uint_as_float(hi));
    return make_float2(__uint_as_float(hi), __uint_as_float(lo));
}

__device__ __forceinline__ void mma_tf32(float* c, const unsigned* a, const unsigned* b) {
    asm volatile(
        "mma.sync.aligned.m16n8k8.row.col.f32.tf32.tf32.f32 "
        "{%0,%1,%2,%3}, {%4,%5,%6,%7}, {%8,%9}, {%0,%1,%2,%3};\n"
        : "+f"(c[0]), "+f"(c[1]), "+f"(c[2]), "+f"(c[3])
        : "r"(a[0]), "r"(a[1]), "r"(a[2]), "r"(a[3]), "r"(b[0]), "r"(b[1]));
}

#define AW 264                       // 2*128 + 8 pad floats per k-row
#define GEMM_BUF_FLOATS (16*AW)      // one buffer, one matrix
#define GEMM_SMEM_BYTES (4 * GEMM_BUF_FLOATS * 2 * 2)   // A+B, double buffered

// stage a 128(rows) x 16(k) fp32 tile from row-major src (ld = row stride) into
// interleaved hi/lo smem. rows are M rows (or N rows for TRANSB=1).
__device__ __forceinline__ void stage_rowmajor(const float* __restrict__ src, int ld,
                                               int r0, int k0, float* dst, int tid) {
    #pragma unroll
    for (int e = 0; e < 2; e++) {
        int idx = tid + e*256;
        int m  = idx & 127;
        int kq = (idx >> 7) << 2;     // 0,4,8,12
        float4 v = *(const float4*)&src[(size_t)(r0+m)*ld + k0 + kq];
        float f[4] = {v.x, v.y, v.z, v.w};
        #pragma unroll
        for (int i = 0; i < 4; i++)
            *(float2*)&dst[(kq+i)*AW + 2*m] = split_tf2(f[i]);
    }
}

// stage a 16(k) x 128(n) fp32 tile from row-major src[K][N] into interleaved hi/lo smem.
__device__ __forceinline__ void stage_colmajor(const float* __restrict__ src, int ld,
                                               int n0, int k0, float* dst, int tid) {
    #pragma unroll
    for (int e = 0; e < 8; e++) {
        int idx = tid + e*256;
        int n = idx & 127;
        int k = idx >> 7;             // 0..15
        float f = src[(size_t)(k0+k)*ld + n0 + n];
        *(float2*)&dst[k*AW + 2*n] = split_tf2(f);
    }
}

template<int TRANSB, int ACC>
__global__ void __launch_bounds__(256)
gemm_tf32x3_kernel(const float* __restrict__ A, const float* __restrict__ B,
                   float* __restrict__ C, int M, int N, int K) {
    extern __shared__ float sm[];
    float* As = sm;                              // [2][16][AW]
    float* Bs = sm + 2*GEMM_BUF_FLOATS;          // [2][16][AW]

    int tid  = threadIdx.x;
    int lane = tid & 31;
    int gr   = lane >> 2;     // 0..7
    int tg   = lane & 3;      // 0..3
    int wid  = tid >> 5;      // 0..7
    int wm   = (wid >> 1) * 32;
    int wn   = (wid & 1) * 64;
    int m0   = blockIdx.y << 7;
    int n0   = blockIdx.x << 7;

    float acc[2][8][4];
    #pragma unroll
    for (int mi = 0; mi < 2; mi++)
        #pragma unroll
        for (int ni = 0; ni < 8; ni++)
            #pragma unroll
            for (int r = 0; r < 4; r++) acc[mi][ni][r] = 0.f;

    const int nk = K >> 4;

    // prologue: chunk 0 -> buffer 0
    stage_rowmajor(A, K, m0, 0, As, tid);
    if (!TRANSB) stage_colmajor(B, N, n0, 0, Bs, tid);
    else         stage_rowmajor(B, K, n0, 0, Bs, tid);
    __syncthreads();

    for (int kc = 0; kc < nk; kc++) {
        int buf = kc & 1;
        if (kc + 1 < nk) {
            int k0 = (kc + 1) << 4;
            int nb = buf ^ 1;
            stage_rowmajor(A, K, m0, k0, As + nb*GEMM_BUF_FLOATS, tid);
            if (!TRANSB) stage_colmajor(B, N, n0, k0, Bs + nb*GEMM_BUF_FLOATS, tid);
            else         stage_rowmajor(B, K, n0, k0, Bs + nb*GEMM_BUF_FLOATS, tid);
        }

        const float* Ab = As + buf*GEMM_BUF_FLOATS;
        const float* Bb = Bs + buf*GEMM_BUF_FLOATS;
        #pragma unroll
        for (int ks = 0; ks < 2; ks++) {
            int kb = ks << 3;
            unsigned ah[2][4], al[2][4];
            #pragma unroll
            for (int mi = 0; mi < 2; mi++) {
                int mb = wm + mi*16;
                float2 t0 = *(const float2*)&Ab[(kb+tg  )*AW + 2*(mb+gr  )];
                float2 t1 = *(const float2*)&Ab[(kb+tg  )*AW + 2*(mb+gr+8)];
                float2 t2 = *(const float2*)&Ab[(kb+tg+4)*AW + 2*(mb+gr  )];
                float2 t3 = *(const float2*)&Ab[(kb+tg+4)*AW + 2*(mb+gr+8)];
                ah[mi][0] = __float_as_uint(t0.x); al[mi][0] = __float_as_uint(t0.y);
                ah[mi][1] = __float_as_uint(t1.x); al[mi][1] = __float_as_uint(t1.y);
                ah[mi][2] = __float_as_uint(t2.x); al[mi][2] = __float_as_uint(t2.y);
                ah[mi][3] = __float_as_uint(t3.x); al[mi][3] = __float_as_uint(t3.y);
            }
            #pragma unroll
            for (int ni = 0; ni < 8; ni++) {
                int nb2 = wn + ni*8 + gr;
                float2 t0 = *(const float2*)&Bb[(kb+tg  )*AW + 2*nb2];
                float2 t1 = *(const float2*)&Bb[(kb+tg+4)*AW + 2*nb2];
                unsigned bh[2] = {__float_as_uint(t0.x), __float_as_uint(t1.x)};
                unsigned bl[2] = {__float_as_uint(t0.y), __float_as_uint(t1.y)};
                #pragma unroll
                for (int mi = 0; mi < 2; mi++) {
                    mma_tf32(acc[mi][ni], al[mi], bh);
                    mma_tf32(acc[mi][ni], ah[mi], bl);
                    mma_tf32(acc[mi][ni], ah[mi], bh);
                }
            }
        }
        __syncthreads();
    }

    // epilogue
    #pragma unroll
    for (int mi = 0; mi < 2; mi++) {
        int r0 = m0 + wm + mi*16 + gr;
        #pragma unroll
        for (int ni = 0; ni < 8; ni++) {
            int c0 = n0 + wn + ni*8 + tg*2;
            float* p0 = &C[(size_t)r0*N + c0];
            float* p1 = &C[(size_t)(r0+8)*N + c0];
            if (ACC) {
                p0[0] += acc[mi][ni][0]; p0[1] += acc[mi][ni][1];
                p1[0] += acc[mi][ni][2]; p1[1] += acc[mi][ni][3];
            } else {
                p0[0] = acc[mi][ni][0]; p0[1] = acc[mi][ni][1];
                p1[0] = acc[mi][ni][2]; p1[1] = acc[mi][ni][3];
            }
        }
    }
}

// ---------------- fused flash attention ----------------
// One CTA per (b,h, 64-row i-tile). Online softmax over causal j-tiles.
// Thread layout: tx = tid&15 (4 d/j cols), ty = tid>>4 (4 rows).
#define ATTN_SMEM_BYTES ((3*64*65 + 64*64) * 4)

__global__ void __launch_bounds__(256)
attn_fused_kernel() {
    extern __shared__ float sm[];
    float (*Qs)[65] = (float(*)[65])sm;
    float (*Ks)[65] = (float(*)[65])(sm + 64*65);
    float (*Ps)[65] = (float(*)[65])(sm + 2*64*65);
    float (*Vs)[64] = (float(*)[64])(sm + 3*64*65);

    int bh = blockIdx.z;
    int b = bh >> 4, h = bh & 15;
    int it = blockIdx.y;
    int i0 = it << 6;
    int tid = threadIdx.x;
    int tx = tid & 15, ty = tid >> 4;

    #pragma unroll
    for (int e = 0; e < 16; e++) {
        int lin = tid + e*256;
        int r = lin >> 6, c = lin & 63;
        Qs[r][c] = g_q[(size_t)(b*SS + i0 + r)*DD + h*HD + c];
    }

    float m_run[4], l_run[4], o[4][4];
    #pragma unroll
    for (int i = 0; i < 4; i++) {
        m_run[i] = -1e30f; l_run[i] = 0.f;
        #pragma unroll
        for (int j = 0; j < 4; j++) o[i][j] = 0.f;
    }

    for (int jt = 0; jt <= it; jt++) {
        int j0 = jt << 6;
        #pragma unroll
        for (int e = 0; e < 16; e++) {
            int lin = tid + e*256;
            int r = lin >> 6, c = lin & 63;
            Ks[r][c] = g_k[(size_t)(b*SS + j0 + r)*DD + h*HD + c];
            Vs[r][c] = g_v[(size_t)(b*SS + j0 + r)*DD + h*HD + c];
        }
        __syncthreads();

        // S = Q K^T (4x4 per thread)
        float s[4][4] = {};
        #pragma unroll 8
        for (int kk = 0; kk < 64; kk++) {
            float a[4], bb[4];
            #pragma unroll
            for (int i = 0; i < 4; i++) a[i]  = Qs[ty*4+i][kk];
            #pragma unroll
            for (int j = 0; j < 4; j++) bb[j] = Ks[tx*4+j][kk];
            #pragma unroll
            for (int i = 0; i < 4; i++)
                #pragma unroll
                for (int j = 0; j < 4; j++)
                    s[i][j] += a[i]*bb[j];
        }

        // scale + causal mask
        #pragma unroll
        for (int i = 0; i < 4; i++) {
            int gi = i0 + ty*4 + i;
            #pragma unroll
            for (int j = 0; j < 4; j++) {
                int gj = j0 + tx*4 + j;
                s[i][j] = (gj > gi) ? -1e30f : s[i][j]*0.125f;
            }
        }

        // online softmax update
        #pragma unroll
        for (int i = 0; i < 4; i++) {
            float mloc = fmaxf(fmaxf(s[i][0], s[i][1]), fmaxf(s[i][2], s[i][3]));
            #pragma unroll
            for (int off = 8; off > 0; off >>= 1)
                mloc = fmaxf(mloc, __shfl_xor_sync(0xffffffffu, mloc, off));
            float m_new = fmaxf(m_run[i], mloc);
            float corr = __expf(m_run[i] - m_new);
            l_run[i] *= corr;
            #pragma unroll
            for (int j = 0; j < 4; j++) o[i][j] *= corr;
            float rs = 0.f;
            #pragma unroll
            for (int j = 0; j < 4; j++) {
                s[i][j] = __expf(s[i][j] - m_new);
                rs += s[i][j];
            }
            #pragma unroll
            for (int off = 8; off > 0; off >>= 1)
                rs += __shfl_xor_sync(0xffffffffu, rs, off);
            l_run[i] += rs;
            m_run[i] = m_new;
        }

        // write P tile
        #pragma unroll
        for (int i = 0; i < 4; i++)
            #pragma unroll
            for (int j = 0; j < 4; j++)
                Ps[ty*4+i][tx*4+j] = s[i][j];
        __syncthreads();

        // O += P V
        #pragma unroll 8
        for (int kk = 0; kk < 64; kk++) {
            float a[4];
            #pragma unroll
            for (int i = 0; i < 4; i++) a[i] = Ps[ty*4+i][kk];
            float4 v4 = *(const float4*)&Vs[kk][tx*4];
            float bv[4] = {v4.x, v4.y, v4.z, v4.w};
            #pragma unroll
            for (int i = 0; i < 4; i++)
                #pragma unroll
                for (int j = 0; j < 4; j++)
                    o[i][j] += a[i]*bv[j];
        }
        __syncthreads();
    }

    #pragma unroll
    for (int i = 0; i < 4; i++) {
        float inv = 1.0f / l_run[i];
        #pragma unroll
        for (int j = 0; j < 4; j++)
            g_ao[(size_t)(b*SS + i0 + ty*4 + i)*DD + h*HD + tx*4 + j] = o[i][j]*inv;
    }
}

// ---------------- host launcher ----------------
extern "C" void kernel_launch(void* const* d_in, const int* in_sizes, int n_in,
                              void* d_out, int out_size) {
    const int*   tokens     = (const int*)  d_in[0];
    const float* emb        = (const float*)d_in[1];
    const float* wq         = (const float*)d_in[2];
    const float* wk         = (const float*)d_in[3];
    const float* wv         = (const float*)d_in[4];
    const float* wo         = (const float*)d_in[5];
    const float* w1         = (const float*)d_in[6];
    const float* w2         = (const float*)d_in[7];
    const float* w3         = (const float*)d_in[8];
    const float* attn_norm  = (const float*)d_in[9];
    const float* ffn_norm   = (const float*)d_in[10];
    const float* final_norm = (const float*)d_in[11];
    float* out = (float*)d_out;
    (void)in_sizes; (void)n_in; (void)out_size;

    float *p_h, *p_hn, *p_q, *p_k, *p_v, *p_ao, *p_f1, *p_f3;
    cudaGetSymbolAddress((void**)&p_h,  g_h);
    cudaGetSymbolAddress((void**)&p_hn, g_hn);
    cudaGetSymbolAddress((void**)&p_q,  g_q);
    cudaGetSymbolAddress((void**)&p_k,  g_k);
    cudaGetSymbolAddress((void**)&p_v,  g_v);
    cudaGetSymbolAddress((void**)&p_ao, g_ao);
    cudaGetSymbolAddress((void**)&p_f1, g_f1);
    cudaGetSymbolAddress((void**)&p_f3, g_f3);

    cudaFuncSetAttribute(gemm_tf32x3_kernel<0,0>, cudaFuncAttributeMaxDynamicSharedMemorySize, GEMM_SMEM_BYTES);
    cudaFuncSetAttribute(gemm_tf32x3_kernel<0,1>, cudaFuncAttributeMaxDynamicSharedMemorySize, GEMM_SMEM_BYTES);
    cudaFuncSetAttribute(gemm_tf32x3_kernel<1,0>, cudaFuncAttributeMaxDynamicSharedMemorySize, GEMM_SMEM_BYTES);
    cudaFuncSetAttribute(attn_fused_kernel,       cudaFuncAttributeMaxDynamicSharedMemorySize, ATTN_SMEM_BYTES);

    rope_tables_kernel<<<(SS*(HD/2)+255)/256, 256>>>();
    embed_kernel<<<(MROWS*DD+255)/256, 256>>>(tokens, emb);

    for (int l = 0; l < LL; l++) {
        // attention block
        rmsnorm_kernel<<<MROWS, 256>>>(p_h, attn_norm + l*DD, p_hn);
        gemm_tf32x3_kernel<0,0><<<dim3(DD/128, MROWS/128), 256, GEMM_SMEM_BYTES>>>(p_hn, wq + (size_t)l*DD*DD, p_q, MROWS, DD, DD);
        gemm_tf32x3_kernel<0,0><<<dim3(DD/128, MROWS/128), 256, GEMM_SMEM_BYTES>>>(p_hn, wk + (size_t)l*DD*DD, p_k, MROWS, DD, DD);
        gemm_tf32x3_kernel<0,0><<<dim3(DD/128, MROWS/128), 256, GEMM_SMEM_BYTES>>>(p_hn, wv + (size_t)l*DD*DD, p_v, MROWS, DD, DD);
        rope_kernel<<<(BB*SS*HH*(HD/2)+255)/256, 256>>>(p_q);
        rope_kernel<<<(BB*SS*HH*(HD/2)+255)/256, 256>>>(p_k);
        attn_fused_kernel<<<dim3(1, SS/64, BB*HH), 256, ATTN_SMEM_BYTES>>>();
        gemm_tf32x3_kernel<0,1><<<dim3(DD/128, MROWS/128), 256, GEMM_SMEM_BYTES>>>(p_ao, wo + (size_t)l*DD*DD, p_h, MROWS, DD, DD);

        // FFN block
        rmsnorm_kernel<<<MROWS, 256>>>(p_h, ffn_norm + l*DD, p_hn);
        gemm_tf32x3_kernel<0,0><<<dim3(FFD/128, MROWS/128), 256, GEMM_SMEM_BYTES>>>(p_hn, w1 + (size_t)l*DD*FFD, p_f1, MROWS, FFD, DD);
        gemm_tf32x3_kernel<0,0><<<dim3(FFD/128, MROWS/128), 256, GEMM_SMEM_BYTES>>>(p_hn, w3 + (size_t)l*DD*FFD, p_f3, MROWS, FFD, DD);
        silu_mul_kernel<<<(MROWS*FFD+255)/256, 256>>>();
        gemm_tf32x3_kernel<0,1><<<dim3(DD/128, MROWS/128), 256, GEMM_SMEM_BYTES>>>(p_f1, w2 + (size_t)l*FFD*DD, p_h, MROWS, DD, FFD);
    }

    rmsnorm_kernel<<<MROWS, 256>>>(p_h, final_norm, p_hn);
    gemm_tf32x3_kernel<1,0><<<dim3(VV/128, MROWS/128), 256, GEMM_SMEM_BYTES>>>(p_hn, emb, out, MROWS, VV, DD);
}